// round 16
// baseline (speedup 1.0000x reference)
#include <cuda_runtime.h>
#include <cstdint>

// out[n,o] = (sum_k xq[n,k]*wq[o,k]) * sx*sw + bias[o]
// xq = round(x * 127/max|x|) clamped [-128,127]; same for w.
// lut[i][j] == (i-128)*(j-128) -> gather is algebraically int8 multiply.
// N = IN = OUT = 512.
// K1 (R14): slot-based absmax+quant, hierarchical atomics + 2-level barrier.
//   Calls cudaTriggerProgrammaticLaunchCompletion() at entry so K2 can ramp.
// K2 (R12 GEMM): launched with ProgrammaticStreamSerialization; runs its
//   preamble concurrently with K1, then cudaGridDependencySynchronize().

#define OO 512

// ---- device scratch (no allocations allowed) ----
__device__ int g_mx8[8 * 64];       // per-slot absmax bits of |x| (256B-strided)
__device__ int g_mw8[8 * 64];       // per-slot absmax bits of |w|
__device__ unsigned g_leaf[8 * 64]; // leaf barrier counters (monotonic)
__device__ unsigned g_root;         // root barrier counter (monotonic)
__device__ int g_maxx;              // final max bits (same-value race: benign)
__device__ int g_maxw;
__device__ int g_xa[512 * 128];     // A fragments: [rt16][kt32] x 32 lanes x 4 ints
__device__ int g_wb[512 * 128];     // B fragments: [ct8][kt32] x 32 lanes x 2 ints

__device__ __forceinline__ int quant1(float v, float inv) {
    int q = __float2int_rn(v * inv);
    q = max(-128, min(127, q));
    return q & 0xFF;
}
__device__ __forceinline__ int pack4(float4 v, float inv) {
    return quant1(v.x, inv) | (quant1(v.y, inv) << 8) |
           (quant1(v.z, inv) << 16) | (quant1(v.w, inv) << 24);
}

__device__ __forceinline__ void mma_s8(int* c, const int4 a, const int2 b) {
    asm volatile(
        "mma.sync.aligned.m16n8k32.row.col.s32.s8.s8.s32 "
        "{%0,%1,%2,%3}, {%4,%5,%6,%7}, {%8,%9}, {%0,%1,%2,%3};"
        : "+r"(c[0]), "+r"(c[1]), "+r"(c[2]), "+r"(c[3])
        : "r"(a.x), "r"(a.y), "r"(a.z), "r"(a.w), "r"(b.x), "r"(b.y));
}

// ------------------------------------------------------------------
// K1: 128 blocks x 256 threads (1 block/SM). R14 body + early PDL trigger.
// ------------------------------------------------------------------
__global__ __launch_bounds__(256, 2)
void quant_kernel(const float4* __restrict__ x4, const float4* __restrict__ w4) {
    __shared__ float sred[8];
    __shared__ float sscale;
    const int tid = threadIdx.x;
    const int bx  = blockIdx.x;

#if __CUDA_ARCH__ >= 900
    if (tid == 0) cudaTriggerProgrammaticLaunchCompletion();
#endif

    const bool isA = bx < 64;
    const int g = (bx & 63) * 256 + tid;    // 0..16383 within side

    float4 v0, v1, v2, v3;
    if (isA) {
        int s = g;
        int rt = s >> 9, kt = (s >> 5) & 15, l = s & 31;
        int r  = rt * 16 + (l >> 2);
        int kw = l & 3;
        int off = r * 128 + kt * 8;
        v0 = x4[off + kw];                // (r,   kw)   -> j0
        v1 = x4[off + 1024 + kw];         // (r+8, kw)   -> j1
        v2 = x4[off + kw + 4];            // (r,   kw+4) -> j2
        v3 = x4[off + 1024 + kw + 4];     // (r+8, kw+4) -> j3
    } else {
        int sb = g << 1;                  // even slot
        int ct = sb >> 9, kt = (sb >> 5) & 15, l = sb & 31;
        int c  = ct * 8 + (l >> 2);
        int kw = l & 3;                   // even (0 or 2)
        int off = c * 128 + kt * 8;
        v0 = w4[off + kw];                // slot 2p: (c, kw)
        v1 = w4[off + kw + 4];            // slot 2p: (c, kw+4)
        v2 = w4[off + kw + 1];            // slot 2p+1: (c, kw+1)
        v3 = w4[off + kw + 5];            // slot 2p+1: (c, kw+5)
    }

    float m = fmaxf(fmaxf(fmaxf(fabsf(v0.x), fabsf(v0.y)),
                          fmaxf(fabsf(v0.z), fabsf(v0.w))),
                    fmaxf(fmaxf(fabsf(v1.x), fabsf(v1.y)),
                          fmaxf(fabsf(v1.z), fabsf(v1.w))));
    m = fmaxf(m, fmaxf(fmaxf(fabsf(v2.x), fabsf(v2.y)),
                       fmaxf(fabsf(v2.z), fabsf(v2.w))));
    m = fmaxf(m, fmaxf(fmaxf(fabsf(v3.x), fabsf(v3.y)),
                       fmaxf(fabsf(v3.z), fabsf(v3.w))));
    #pragma unroll
    for (int o = 16; o > 0; o >>= 1)
        m = fmaxf(m, __shfl_xor_sync(0xFFFFFFFFu, m, o));
    if ((tid & 31) == 0) sred[tid >> 5] = m;
    __syncthreads();

    // hierarchical atomics + 2-level barrier (thread 0 only)
    if (tid == 0) {
        float bm = sred[0];
        #pragma unroll
        for (int i = 1; i < 8; ++i) bm = fmaxf(bm, sred[i]);
        const int slot = (bx & 7) * 64;       // 256B-strided
        atomicMax(isA ? &g_mx8[slot] : &g_mw8[slot], __float_as_int(bm));
        __threadfence();
        unsigned a = atomicAdd(&g_leaf[slot], 1u) + 1u;   // 16 arrivals/leaf/round
        unsigned n = (a + 15u) >> 4;                      // my round number
        if (a == (n << 4)) atomicAdd(&g_root, 1u);        // last of leaf -> root
        while (*(volatile unsigned*)&g_root < (n << 3)) { }  // 8 leaves/round
        __threadfence();
        const int* slots = isA ? g_mx8 : g_mw8;
        int fb = slots[0];
        #pragma unroll
        for (int i = 1; i < 8; ++i) fb = max(fb, slots[i * 64]);
        *(isA ? &g_maxx : &g_maxw) = fb;     // same-value race: benign
        sscale = 127.0f / __int_as_float(fb);
    }
    __syncthreads();

    const float inv = sscale;
    int4 o;
    o.x = pack4(v0, inv);
    o.y = pack4(v1, inv);
    o.z = pack4(v2, inv);
    o.w = pack4(v3, inv);
    ((int4*)(isA ? g_xa : g_wb))[g] = o;
}

// ------------------------------------------------------------------
// K2: IMMA GEMM (R12 config). Preamble (indices + bias load) runs under PDL
// overlap; cudaGridDependencySynchronize() before consuming K1's fragments.
// ------------------------------------------------------------------
__global__ __launch_bounds__(256, 2)
void gemm_kernel(const float* __restrict__ bias, float* __restrict__ out) {
    const int tid  = threadIdx.x;
    const int wid  = tid >> 5;
    const int lane = tid & 31;
    const int rt   = (blockIdx.x >> 4) * 2 + (wid >> 2);  // 0..31
    const int ct   = (blockIdx.x & 15) * 4 + (wid & 3);   // 0..63

    const int4* __restrict__ XA = (const int4*)g_xa;
    const int2* __restrict__ WB = (const int2*)g_wb;

    // K1-independent preamble: bias load (input, untouched by K1)
    const int g   = lane >> 2;       // row within tile
    const int tig = lane & 3;        // col pair
    const int col = ct * 8 + tig * 2;
    const float2 bb = *(const float2*)&bias[col];

#if __CUDA_ARCH__ >= 900
    cudaGridDependencySynchronize();   // wait for K1 completion + visibility
#endif

    int acc[4] = {0, 0, 0, 0};

    #pragma unroll
    for (int kt = 0; kt < 16; ++kt) {
        int4 a = XA[(rt * 16 + kt) * 32 + lane];
        int2 b = WB[(ct * 16 + kt) * 32 + lane];
        mma_s8(acc, a, b);
    }

    const float fmx = __int_as_float(g_maxx);
    const float fmw = __int_as_float(g_maxw);
    const float sc  = (fmx / 127.0f) * (fmw / 127.0f);
    {
        int row = rt * 16 + g;
        float2 v0 = { (float)acc[0] * sc + bb.x, (float)acc[1] * sc + bb.y };
        float2 v1 = { (float)acc[2] * sc + bb.x, (float)acc[3] * sc + bb.y };
        *(float2*)&out[row * OO + col]       = v0;
        *(float2*)&out[(row + 8) * OO + col] = v1;
    }
}

// ------------------------------------------------------------------
extern "C" void kernel_launch(void* const* d_in, const int* in_sizes, int n_in,
                              void* d_out, int out_size) {
    const float* x    = (const float*)d_in[0];   // [512,512]
    const float* w    = (const float*)d_in[1];   // [512,512]
    const float* bias = (const float*)d_in[2];   // [512]
    float* out = (float*)d_out;

    // K1: normal launch
    quant_kernel<<<128, 256>>>((const float4*)x, (const float4*)w);

    // K2: PDL launch — may begin ramping as soon as K1 triggers
    cudaLaunchConfig_t cfg = {};
    cfg.gridDim  = dim3(256, 1, 1);
    cfg.blockDim = dim3(256, 1, 1);
    cfg.dynamicSmemBytes = 0;
    cfg.stream = 0;                       // thread-local default stream (captured)
    cudaLaunchAttribute attrs[1];
    attrs[0].id = cudaLaunchAttributeProgrammaticStreamSerialization;
    attrs[0].val.programmaticStreamSerializationAllowed = 1;
    cfg.attrs = attrs;
    cfg.numAttrs = 1;
    cudaLaunchKernelEx(&cfg, gemm_kernel, bias, out);
}